// round 3
// baseline (speedup 1.0000x reference)
#include <cuda_runtime.h>
#include <cuda_fp16.h>

#define NB 8
#define NC 12
#define GD 8
#define GH 16
#define GW 16
#define IH 1024
#define IW 1024

// Transposed grid (fp32): [n][y][x][z][c], c contiguous
__device__ float g_t[NB * GH * GW * GD * NC];

// src layout: [n][c][z][y][x]
__global__ __launch_bounds__(256) void transpose_grid_kernel(const float* __restrict__ src) {
    int idx = blockIdx.x * 256 + threadIdx.x;
    if (idx >= NB * NC * GD * GH * GW) return;
    int x = idx & 15;
    int y = (idx >> 4) & 15;
    int z = (idx >> 8) & 7;
    int c = (idx >> 11) % NC;
    int n = idx / (NC * GD * GH * GW);
    g_t[((((n * GH + y) * GW + x) * GD + z) * NC) + c] = src[idx];
}

// smem line: fp16, per (x,z) a 16-half slot (12 used), x-stride 136 halfs
#define ZS 16     // halfs per (x,z) slot
#define XS 136    // halfs per x (8*16 + 8 pad)

// Load 12 halfs (1x LDS.128 + 1x LDS.64) and convert to 12 floats
__device__ __forceinline__ void ld12h(const __half* p, float* f) {
    uint4 a = *reinterpret_cast<const uint4*>(p);
    uint2 b = *reinterpret_cast<const uint2*>(p + 8);
    float2 t;
    t = __half22float2(*reinterpret_cast<const __half2*>(&a.x)); f[0] = t.x; f[1] = t.y;
    t = __half22float2(*reinterpret_cast<const __half2*>(&a.y)); f[2] = t.x; f[3] = t.y;
    t = __half22float2(*reinterpret_cast<const __half2*>(&a.z)); f[4] = t.x; f[5] = t.y;
    t = __half22float2(*reinterpret_cast<const __half2*>(&a.w)); f[6] = t.x; f[7] = t.y;
    t = __half22float2(*reinterpret_cast<const __half2*>(&b.x)); f[8] = t.x; f[9] = t.y;
    t = __half22float2(*reinterpret_cast<const __half2*>(&b.y)); f[10] = t.x; f[11] = t.y;
}

__global__ __launch_bounds__(256) void slice_kernel(
    const float* __restrict__ guide,   // [n][i][j]
    float* __restrict__ out)           // [n][c][i][j]
{
    __shared__ __align__(16) __half sm[GW * XS];   // 16*136*2 = 4352 B

    int bid = blockIdx.x;              // n*1024 + i
    int n = bid >> 10;
    int i = bid & 1023;
    int tid = threadIdx.x;

    // ---- y-interp precompute (fp32 math, fp16 store) ----
    float gy = ((float)i + 0.5f) * (16.0f / 1024.0f);
    float fy = floorf(gy - 0.5f);
    float wy1 = gy - 0.5f - fy;
    int iy = (int)fy;
    int y0 = max(0, min(GH - 1, iy));
    int y1 = max(0, min(GH - 1, iy + 1));

    const float2* r0 = (const float2*)(g_t + ((size_t)(n * GH + y0) * GW) * (GD * NC));
    const float2* r1 = (const float2*)(g_t + ((size_t)(n * GH + y1) * GW) * (GD * NC));
    __half2* smv = (__half2*)sm;   // x stride = 68 half2, z stride = 8 half2

    // 16x * 8z * 6 half2 = 768 elements
#pragma unroll
    for (int v = tid; v < GW * 48; v += 256) {
        int x = v / 48;
        int zc2 = v - x * 48;          // z*6 + c2
        int z = zc2 / 6;
        int c2 = zc2 - z * 6;
        float2 a = r0[v];
        float2 b = r1[v];
        float ox = fmaf(wy1, b.x - a.x, a.x);
        float oy = fmaf(wy1, b.y - a.y, a.y);
        smv[x * 68 + z * 8 + c2] = __floats2half2_rn(ox, oy);
    }
    __syncthreads();

    // ---- 4 pixels per thread, strided by 256 (coalesced I/O) ----
    const float* grow = guide + (((size_t)n << 10) + i) * 1024;
    size_t obase = (((size_t)(n * NC)) << 20) + ((size_t)i << 10);

#pragma unroll
    for (int p = 0; p < 4; p++) {
        int j = tid + (p << 8);
        float g = grow[j];

        float gx = ((float)j + 0.5f) * (16.0f / 1024.0f);
        float fx = floorf(gx - 0.5f);
        float wx1 = gx - 0.5f - fx;
        int ix = (int)fx;
        int x0 = max(0, min(GW - 1, ix));
        int x1 = max(0, min(GW - 1, ix + 1));

        float gz = g * 8.0f;
        float fz = floorf(gz - 0.5f);
        float wz1 = gz - 0.5f - fz;
        int iz = (int)fz;
        int z0 = max(0, min(GD - 1, iz));
        int z1 = max(0, min(GD - 1, iz + 1));

        float wx0 = 1.0f - wx1;
        float wz0 = 1.0f - wz1;
        float w00 = wx0 * wz0;
        float w01 = wx0 * wz1;
        float w10 = wx1 * wz0;
        float w11 = wx1 * wz1;

        const __half* A = sm + x0 * XS;
        const __half* B = sm + x1 * XS;

        float f00[12], f01[12], f10[12], f11[12];
        ld12h(A + z0 * ZS, f00);
        ld12h(A + z1 * ZS, f01);
        ld12h(B + z0 * ZS, f10);
        ld12h(B + z1 * ZS, f11);

        int off = (i << 10) | j;
#pragma unroll
        for (int c = 0; c < 12; c++) {
            float o = w00 * f00[c] + w01 * f01[c] + w10 * f10[c] + w11 * f11[c];
            out[obase + (((size_t)c) << 20) + ((size_t)j)] = o;
        }
        (void)off;
    }
}

extern "C" void kernel_launch(void* const* d_in, const int* in_sizes, int n_in,
                              void* d_out, int out_size) {
    const float* grid_src = nullptr;
    const float* guide = nullptr;
    for (int k = 0; k < n_in; k++) {
        if (in_sizes[k] == NB * NC * GD * GH * GW) grid_src = (const float*)d_in[k];
        else if (in_sizes[k] == NB * IH * IW) guide = (const float*)d_in[k];
    }
    float* out = (float*)d_out;

    int ne = NB * NC * GD * GH * GW;
    transpose_grid_kernel<<<(ne + 255) / 256, 256>>>(grid_src);

    slice_kernel<<<NB * IH, 256>>>(guide, out);
}

// round 4
// speedup vs baseline: 1.0172x; 1.0172x over previous
#include <cuda_runtime.h>
#include <cuda_fp16.h>

#define NB 8
#define NC 12
#define GD 8
#define GH 16
#define GW 16
#define IH 1024
#define IW 1024

// Transposed grid (fp32): [n][y][x][z][c], c contiguous
__device__ float g_t[NB * GH * GW * GD * NC];

// src layout: [n][c][z][y][x]
__global__ __launch_bounds__(256) void transpose_grid_kernel(const float* __restrict__ src) {
    int idx = blockIdx.x * 256 + threadIdx.x;
    if (idx >= NB * NC * GD * GH * GW) return;
    int x = idx & 15;
    int y = (idx >> 4) & 15;
    int z = (idx >> 8) & 7;
    int c = (idx >> 11) % NC;
    int n = idx / (NC * GD * GH * GW);
    g_t[((((n * GH + y) * GW + x) * GD + z) * NC) + c] = src[idx];
}

// Conflict-free fp16 line layout:
//   z-stride = 24 halfs = 48 B  (12 used + 12 pad)  -> z*12 banks, z*3 granules mod 8: all distinct
//   x-stride = 200 halfs = 400 B (8*24 + 8 pad)     -> +1 granule per x
#define ZS 24     // halfs per (x,z) slot
#define XS 200    // halfs per x

// Load 12 halfs (LDS.128 + LDS.64) and convert to 12 floats
__device__ __forceinline__ void ld12h(const __half* p, float* f) {
    uint4 a = *reinterpret_cast<const uint4*>(p);
    uint2 b = *reinterpret_cast<const uint2*>(p + 8);
    float2 t;
    t = __half22float2(*reinterpret_cast<const __half2*>(&a.x)); f[0] = t.x;  f[1] = t.y;
    t = __half22float2(*reinterpret_cast<const __half2*>(&a.y)); f[2] = t.x;  f[3] = t.y;
    t = __half22float2(*reinterpret_cast<const __half2*>(&a.z)); f[4] = t.x;  f[5] = t.y;
    t = __half22float2(*reinterpret_cast<const __half2*>(&a.w)); f[6] = t.x;  f[7] = t.y;
    t = __half22float2(*reinterpret_cast<const __half2*>(&b.x)); f[8] = t.x;  f[9] = t.y;
    t = __half22float2(*reinterpret_cast<const __half2*>(&b.y)); f[10] = t.x; f[11] = t.y;
}

__global__ __launch_bounds__(256) void slice_kernel(
    const float* __restrict__ guide,   // [n][i][j]
    float* __restrict__ out)           // [n][c][i][j]
{
    __shared__ __align__(16) __half sm[GW * XS];   // 16*200*2 = 6400 B

    int bid = blockIdx.x;              // n*1024 + i
    int n = bid >> 10;
    int i = bid & 1023;
    int tid = threadIdx.x;

    // ---- y-interp precompute (fp32 math, fp16 store) ----
    float gy = ((float)i + 0.5f) * (16.0f / 1024.0f);
    float fy = floorf(gy - 0.5f);
    float wy1 = gy - 0.5f - fy;
    int iy = (int)fy;
    int y0 = max(0, min(GH - 1, iy));
    int y1 = max(0, min(GH - 1, iy + 1));

    const float2* r0 = (const float2*)(g_t + ((size_t)(n * GH + y0) * GW) * (GD * NC));
    const float2* r1 = (const float2*)(g_t + ((size_t)(n * GH + y1) * GW) * (GD * NC));
    __half2* smv = (__half2*)sm;   // x stride = 100 half2, z stride = 12 half2

    // 16x * 8z * 6 half2 = 768 elements
#pragma unroll
    for (int v = tid; v < GW * 48; v += 256) {
        int x = v / 48;
        int zc2 = v - x * 48;          // z*6 + c2
        int z = zc2 / 6;
        int c2 = zc2 - z * 6;
        float2 a = r0[v];
        float2 b = r1[v];
        float ox = fmaf(wy1, b.x - a.x, a.x);
        float oy = fmaf(wy1, b.y - a.y, a.y);
        smv[x * 100 + z * 12 + c2] = __floats2half2_rn(ox, oy);
    }
    __syncthreads();

    // ---- 4 pixels per thread, strided by 256 (coalesced I/O) ----
    const float* grow = guide + (((size_t)n << 10) + i) * 1024;
    size_t obase = (((size_t)(n * NC)) << 20) + ((size_t)i << 10);

#pragma unroll
    for (int p = 0; p < 4; p++) {
        int j = tid + (p << 8);
        float g = grow[j];

        float gx = ((float)j + 0.5f) * (16.0f / 1024.0f);
        float fx = floorf(gx - 0.5f);
        float wx1 = gx - 0.5f - fx;
        int ix = (int)fx;
        int x0 = max(0, min(GW - 1, ix));
        int x1 = max(0, min(GW - 1, ix + 1));

        float gz = g * 8.0f;
        float fz = floorf(gz - 0.5f);
        float wz1 = gz - 0.5f - fz;
        int iz = (int)fz;
        int z0 = max(0, min(GD - 1, iz));
        int z1 = max(0, min(GD - 1, iz + 1));

        float wx0 = 1.0f - wx1;
        float wz0 = 1.0f - wz1;
        float w00 = wx0 * wz0;
        float w01 = wx0 * wz1;
        float w10 = wx1 * wz0;
        float w11 = wx1 * wz1;

        const __half* A = sm + x0 * XS;
        const __half* B = sm + x1 * XS;

        float f00[12], f01[12], f10[12], f11[12];
        ld12h(A + z0 * ZS, f00);
        ld12h(A + z1 * ZS, f01);
        ld12h(B + z0 * ZS, f10);
        ld12h(B + z1 * ZS, f11);

#pragma unroll
        for (int c = 0; c < 12; c++) {
            float o = w00 * f00[c] + w01 * f01[c] + w10 * f10[c] + w11 * f11[c];
            out[obase + (((size_t)c) << 20) + ((size_t)j)] = o;
        }
    }
}

extern "C" void kernel_launch(void* const* d_in, const int* in_sizes, int n_in,
                              void* d_out, int out_size) {
    const float* grid_src = nullptr;
    const float* guide = nullptr;
    for (int k = 0; k < n_in; k++) {
        if (in_sizes[k] == NB * NC * GD * GH * GW) grid_src = (const float*)d_in[k];
        else if (in_sizes[k] == NB * IH * IW) guide = (const float*)d_in[k];
    }
    float* out = (float*)d_out;

    int ne = NB * NC * GD * GH * GW;
    transpose_grid_kernel<<<(ne + 255) / 256, 256>>>(grid_src);

    slice_kernel<<<NB * IH, 256>>>(guide, out);
}

// round 5
// speedup vs baseline: 1.0424x; 1.0247x over previous
#include <cuda_runtime.h>
#include <cuda_fp16.h>

#define NB 8
#define NC 12
#define GD 8
#define GH 16
#define GW 16
#define IH 1024
#define IW 1024

// Conflict-free fp16 line layout:
//   z-stride = 24 halfs = 48 B (12 used + 12 pad)  -> z*3 granules mod 8 all distinct
//   x-stride = 200 halfs = 400 B
#define ZS 24
#define XS 200

// Load 12 halfs (LDS.128 + LDS.64) and convert to 12 floats
__device__ __forceinline__ void ld12h(const __half* p, float* f) {
    uint4 a = *reinterpret_cast<const uint4*>(p);
    uint2 b = *reinterpret_cast<const uint2*>(p + 8);
    float2 t;
    t = __half22float2(*reinterpret_cast<const __half2*>(&a.x)); f[0] = t.x;  f[1] = t.y;
    t = __half22float2(*reinterpret_cast<const __half2*>(&a.y)); f[2] = t.x;  f[3] = t.y;
    t = __half22float2(*reinterpret_cast<const __half2*>(&a.z)); f[4] = t.x;  f[5] = t.y;
    t = __half22float2(*reinterpret_cast<const __half2*>(&a.w)); f[6] = t.x;  f[7] = t.y;
    t = __half22float2(*reinterpret_cast<const __half2*>(&b.x)); f[8] = t.x;  f[9] = t.y;
    t = __half22float2(*reinterpret_cast<const __half2*>(&b.y)); f[10] = t.x; f[11] = t.y;
}

__global__ __launch_bounds__(256) void slice_kernel(
    const float* __restrict__ grid_src,  // [n][c][z][y][x]
    const float* __restrict__ guide,     // [n][i][j]
    float* __restrict__ out)             // [n][c][i][j]
{
    __shared__ __align__(16) __half sm[GW * XS];   // 6400 B

    int bid = blockIdx.x;              // n*1024 + i
    int n = bid >> 10;
    int i = bid & 1023;
    int tid = threadIdx.x;

    // ---- y-interp + fused transpose: fill smem line directly from src ----
    float gy = ((float)i + 0.5f) * (16.0f / 1024.0f);
    float fy = floorf(gy - 0.5f);
    float wy1 = gy - 0.5f - fy;
    int iy = (int)fy;
    int y0 = max(0, min(GH - 1, iy));
    int y1 = max(0, min(GH - 1, iy + 1));
    int dy = (y1 - y0) * GW;           // offset between the two y-rows (floats)

    const float* gbase = grid_src + (size_t)n * (NC * GD * GH * GW) + y0 * GW;
    __half2* smv = (__half2*)sm;       // x stride 100, z stride 12 (half2 units)

    // 768 half2 outputs: v = (c2*8 + z)*16 + x  (x fastest -> coalesced 64B runs)
#pragma unroll
    for (int v = tid; v < GW * 48; v += 256) {
        int x = v & 15;
        int zc = v >> 4;               // c2*8 + z
        int z = zc & 7;
        int c2 = zc >> 3;
        const float* p = gbase + ((size_t)(c2 * 2) * GD + z) * (GH * GW) + x;
        float a0 = __ldg(p);
        float b0 = __ldg(p + dy);
        float a1 = __ldg(p + GD * GH * GW);
        float b1 = __ldg(p + GD * GH * GW + dy);
        float ox = fmaf(wy1, b0 - a0, a0);
        float oy = fmaf(wy1, b1 - a1, a1);
        smv[x * 100 + z * 12 + c2] = __floats2half2_rn(ox, oy);
    }
    __syncthreads();

    // ---- 4 pixels per thread, strided by 256 (coalesced I/O) ----
    const float* grow = guide + (((size_t)n << 10) + i) * 1024;
    size_t obase = (((size_t)(n * NC)) << 20) + ((size_t)i << 10);

#pragma unroll
    for (int p = 0; p < 4; p++) {
        int j = tid + (p << 8);
        float g = __ldcs(grow + j);

        float gx = ((float)j + 0.5f) * (16.0f / 1024.0f);
        float fx = floorf(gx - 0.5f);
        float wx1 = gx - 0.5f - fx;
        int ix = (int)fx;
        int x0 = max(0, min(GW - 1, ix));
        int x1 = max(0, min(GW - 1, ix + 1));

        float gz = g * 8.0f;
        float fz = floorf(gz - 0.5f);
        float wz1 = gz - 0.5f - fz;
        int iz = (int)fz;
        int z0 = max(0, min(GD - 1, iz));
        int z1 = max(0, min(GD - 1, iz + 1));

        float wx0 = 1.0f - wx1;
        float wz0 = 1.0f - wz1;
        float w00 = wx0 * wz0;
        float w01 = wx0 * wz1;
        float w10 = wx1 * wz0;
        float w11 = wx1 * wz1;

        const __half* A = sm + x0 * XS;
        const __half* B = sm + x1 * XS;

        float f00[12], f01[12], f10[12], f11[12];
        ld12h(A + z0 * ZS, f00);
        ld12h(A + z1 * ZS, f01);
        ld12h(B + z0 * ZS, f10);
        ld12h(B + z1 * ZS, f11);

#pragma unroll
        for (int c = 0; c < 12; c++) {
            float o = w00 * f00[c] + w01 * f01[c] + w10 * f10[c] + w11 * f11[c];
            __stcs(out + obase + (((size_t)c) << 20) + (size_t)j, o);
        }
    }
}

extern "C" void kernel_launch(void* const* d_in, const int* in_sizes, int n_in,
                              void* d_out, int out_size) {
    const float* grid_src = nullptr;
    const float* guide = nullptr;
    for (int k = 0; k < n_in; k++) {
        if (in_sizes[k] == NB * NC * GD * GH * GW) grid_src = (const float*)d_in[k];
        else if (in_sizes[k] == NB * IH * IW) guide = (const float*)d_in[k];
    }
    float* out = (float*)d_out;

    slice_kernel<<<NB * IH, 256>>>(grid_src, guide, out);
}